// round 15
// baseline (speedup 1.0000x reference)
#include <cuda_runtime.h>
#include <cuda_bf16.h>
#include <cstdint>

#define T_STEPS 1000
#define BATCH   64
#define NIN     256
#define NHID    512
#define NOUT    128
#define M_ROWS  (T_STEPS * BATCH)

#define V_TH     (-45.0f)
#define V_DET    (-48.5f)    // detection threshold with fp8-error slack
#define V_RESET  (-60.0f)
#define DT_CM    (0.5f)
#define DECAY_V  (0.05f)
#define D_ASC0   (0.9048374180359595f)
#define D_ASC1   (0.8187307530779818f)
#define D_SYN    (0.8187307530779818f)
#define AMP0     (1.0f)
#define AMP1     (-2.0f)

#define RINV     (1.0526315789473684f)   // 0.95^-1
#define A63      (0.0394991161f)         // 0.95^63
#define A62      (0.0415780170f)         // 0.95^62
#define NSUB     16
#define CSC      (0.00390625f)           // 0.5 / (4*32) fp8 scale compensation

__device__ __align__(128) __nv_bfloat16 g_xproj[(size_t)M_ROWS * NHID]; // fallback only
__device__ __align__(128) uint32_t g_w8[NHID * NIN / 4];                // e4m3 W, FRAGMENT order
__device__ __align__(128) uint4 g_x8[512 * 2048];                       // e4m3 x, per-tile FRAGMENT order (16MB)
__device__ __align__(128) float g_wrecT[NHID * NHID];                   // built by fallback
__device__ __align__(128) float g_chkB[NSUB * BATCH * NHID];
__device__ __align__(128) float g_chkT[NSUB * BATCH * NHID];
__device__ int g_bspike[BATCH];
__device__ int g_any;

static __device__ __forceinline__ uint32_t s2u(const void* p) {
    return (uint32_t)__cvta_generic_to_shared(p);
}
static __device__ __forceinline__ uint32_t pack_e4m3_4(float v0, float v1, float v2, float v3) {
    uint16_t lo, hi;   // cvt packs: low byte = 2nd operand
    asm("cvt.rn.satfinite.e4m3x2.f32 %0, %1, %2;" : "=h"(lo) : "f"(v1), "f"(v0));
    asm("cvt.rn.satfinite.e4m3x2.f32 %0, %1, %2;" : "=h"(hi) : "f"(v3), "f"(v2));
    return (uint32_t)lo | ((uint32_t)hi << 16);
}
static __device__ __forceinline__ uint4 cvt8_bf16(float4 a, float4 b) {
    __nv_bfloat162 p0 = __floats2bfloat162_rn(a.x, a.y);
    __nv_bfloat162 p1 = __floats2bfloat162_rn(a.z, a.w);
    __nv_bfloat162 p2 = __floats2bfloat162_rn(b.x, b.y);
    __nv_bfloat162 p3 = __floats2bfloat162_rn(b.z, b.w);
    return make_uint4(*reinterpret_cast<uint32_t*>(&p0), *reinterpret_cast<uint32_t*>(&p1),
                      *reinterpret_cast<uint32_t*>(&p2), *reinterpret_cast<uint32_t*>(&p3));
}
#define LDSM4(d0, d1, d2, d3, a)                                                 \
    asm volatile("ldmatrix.sync.aligned.m8n8.x4.shared.b16 {%0,%1,%2,%3}, [%4];" \
                 : "=r"(d0), "=r"(d1), "=r"(d2), "=r"(d3) : "r"(a))
#define MMA16816(ac, a0, a1, a2, a3, b0, b1)                                     \
    asm volatile("mma.sync.aligned.m16n8k16.row.col.f32.bf16.bf16.f32 "          \
                 "{%0,%1,%2,%3}, {%4,%5,%6,%7}, {%8,%9}, {%0,%1,%2,%3};\n"       \
                 : "+f"(ac[0]), "+f"(ac[1]), "+f"(ac[2]), "+f"(ac[3])            \
                 : "r"(a0), "r"(a1), "r"(a2), "r"(a3), "r"(b0), "r"(b1))
#define MMAFP8(ac, a0, a1, a2, a3, b0, b1)                                       \
    asm volatile("mma.sync.aligned.m16n8k32.row.col.f32.e4m3.e4m3.f32 "          \
                 "{%0,%1,%2,%3}, {%4,%5,%6,%7}, {%8,%9}, {%0,%1,%2,%3};\n"       \
                 : "+f"(ac[0]), "+f"(ac[1]), "+f"(ac[2]), "+f"(ac[3])            \
                 : "r"(a0), "r"(a1), "r"(a2), "r"(a3), "r"(b0), "r"(b1))

// ---- prep: e4m3 fragment-pack of W + flag resets (65 CTAs) -----------------
__global__ void __launch_bounds__(256) prep_kernel(const float* __restrict__ W_in) {
    const int bid = blockIdx.x, tid = threadIdx.x;
    if (bid == 64) {
        if (tid < BATCH) g_bspike[tid] = 0;
        if (tid == BATCH) g_any = 0;
        return;
    }
    int uu = bid * 256 + tid;                    // < 16384
    int nt8 = uu >> 8, ks = (uu >> 5) & 7, lane = uu & 31;
    int gg = lane >> 2, tg = lane & 3;
    int n = nt8 * 8 + gg;
    int k0 = ks * 32 + tg * 4;
    float4 w0 = *reinterpret_cast<const float4*>(W_in + n * NIN + k0);
    float4 w1 = *reinterpret_cast<const float4*>(W_in + n * NIN + k0 + 16);
    uint2 pk;
    pk.x = pack_e4m3_4(32.f * w0.x, 32.f * w0.y, 32.f * w0.z, 32.f * w0.w);
    pk.y = pack_e4m3_4(32.f * w1.x, 32.f * w1.y, 32.f * w1.z, 32.f * w1.w);
    *reinterpret_cast<uint2*>(reinterpret_cast<char*>(g_w8) + (size_t)uu * 8) = pk;
}

// ---- cvt_x8: x fp32 -> e4m3 in per-(b,chunk) fragment order (2048 CTAs) ----
// tile = cch*64 + b (matches fused blockIdx). unit u in tile:
//   u = (mtile*8 + ks)*32 + lane_u, lane_u = ug*4 + utg
//   rows r0 = mtile*16+ug, r1 = r0+8 (of 125); k0 = ks*32 + utg*4
__global__ void __launch_bounds__(256) cvt_x8_kernel(const float* __restrict__ x) {
#pragma unroll
    for (int i = 0; i < 2; ++i) {
        int U = blockIdx.x * 512 + i * 256 + threadIdx.x;   // < 1,048,576
        int tile = U >> 11, u = U & 2047;
        int b = tile & 63, cch = tile >> 6;
        int t0 = cch * 125;
        int mtile = u >> 8, ks = (u >> 5) & 7, lu = u & 31;
        int ug = lu >> 2, utg = lu & 3;
        int r0 = mtile * 16 + ug, r1 = r0 + 8;
        int k0 = ks * 32 + utg * 4;
        const float* x0 = x + ((long)(t0 + r0) * 64 + b) * NIN;
        float4 q0 = *reinterpret_cast<const float4*>(x0 + k0);
        float4 q2 = *reinterpret_cast<const float4*>(x0 + k0 + 16);
        float4 q1 = make_float4(0.f, 0.f, 0.f, 0.f), q3 = q1;
        if (r1 < 125) {
            const float* x1 = x + ((long)(t0 + r1) * 64 + b) * NIN;
            q1 = *reinterpret_cast<const float4*>(x1 + k0);
            q3 = *reinterpret_cast<const float4*>(x1 + k0 + 16);
        }
        uint4 frag;
        frag.x = pack_e4m3_4(4.f * q0.x, 4.f * q0.y, 4.f * q0.z, 4.f * q0.w);
        frag.y = pack_e4m3_4(4.f * q1.x, 4.f * q1.y, 4.f * q1.z, 4.f * q1.w);
        frag.z = pack_e4m3_4(4.f * q2.x, 4.f * q2.y, 4.f * q2.z, 4.f * q2.w);
        frag.w = pack_e4m3_4(4.f * q3.x, 4.f * q3.y, 4.f * q3.z, 4.f * q3.w);
        g_x8[U] = frag;
    }
}

// ---------------- fused FP8 GEMM + chunk-summary scan (stage A = copy) ------
#define SM_A   0            // 32768
#define SM_B   32768        // 32768
#define SM_TP  65536        // 128 x 136 bf16 = 34816
#define FUSED_SMEM 100352

__global__ void __launch_bounds__(256, 2) fused_kernel() {
    extern __shared__ char smem[];
    const int tid = threadIdx.x, warp = tid >> 5, lane = tid & 31;
    const int b = blockIdx.x & 63, cch = blockIdx.x >> 6;   // chunk 0..7
    const int wm = warp & 1, wn = warp >> 1;                // 2m x 4n warps
    const int gg = lane >> 2, tg = lane & 3;

    // ---- stage A: plain 32KB copy from pre-converted g_x8 ----
    const uint4* __restrict__ xa = g_x8 + (size_t)blockIdx.x * 2048;
#pragma unroll
    for (int i = 0; i < 8; ++i) {
        int idx = tid + i * 256;
        *reinterpret_cast<uint4*>(smem + SM_A + (size_t)idx * 16) = xa[idx];
    }

    const uint32_t sA32 = s2u(smem + SM_A);
    const uint32_t sB32 = s2u(smem + SM_B);
    __nv_bfloat16* tp = reinterpret_cast<__nv_bfloat16*>(smem + SM_TP);

    const int q  = tid >> 7, hh = tid & 127;     // half-split ladder
    const int toff = q ? 63 : 0;
    const int len  = q ? 62 : 63;
    const float Afac = q ? A62 : A63;

#pragma unroll 1
    for (int slab = 0; slab < 4; ++slab) {
        __syncthreads();
#pragma unroll
        for (int i = 0; i < 8; ++i) {
            int idx = tid + i * 256;    // uint4 units, 2048 total
            uint4 v = reinterpret_cast<const uint4*>(g_w8)[slab * 2048 + idx];
            *reinterpret_cast<uint4*>(smem + SM_B + (size_t)idx * 16) = v;
        }
        __syncthreads();

        float acc[4][4][4];
#pragma unroll
        for (int a = 0; a < 4; ++a)
#pragma unroll
            for (int b2 = 0; b2 < 4; ++b2)
#pragma unroll
                for (int c = 0; c < 4; ++c) acc[a][b2][c] = 0.f;

#pragma unroll
        for (int ks = 0; ks < 8; ++ks) {
            uint4 af[4];
            uint2 bf[4];
#pragma unroll
            for (int mt = 0; mt < 4; ++mt) {
                uint32_t addr = sA32 + (((wm * 4 + mt) * 8 + ks) * 32 + lane) * 16;
                asm volatile("ld.shared.v4.u32 {%0,%1,%2,%3}, [%4];"
                             : "=r"(af[mt].x), "=r"(af[mt].y),
                               "=r"(af[mt].z), "=r"(af[mt].w) : "r"(addr));
            }
#pragma unroll
            for (int nt = 0; nt < 4; ++nt) {
                uint32_t addr = sB32 + (((wn * 4 + nt) * 8 + ks) * 32 + lane) * 8;
                asm volatile("ld.shared.v2.u32 {%0,%1}, [%2];"
                             : "=r"(bf[nt].x), "=r"(bf[nt].y) : "r"(addr));
            }
#pragma unroll
            for (int mt = 0; mt < 4; ++mt)
#pragma unroll
                for (int nt = 0; nt < 4; ++nt)
                    MMAFP8(acc[mt][nt], af[mt].x, af[mt].y, af[mt].z, af[mt].w,
                           bf[nt].x, bf[nt].y);
        }

        // transpose acc -> tp[t][h'] (prior ladder finished at stage-B sync)
#pragma unroll
        for (int mt = 0; mt < 4; ++mt) {
            int row0 = wm * 64 + mt * 16 + gg;
#pragma unroll
            for (int nt = 0; nt < 4; ++nt) {
                int col = wn * 32 + nt * 8 + tg * 2;
                *reinterpret_cast<__nv_bfloat162*>(tp + row0 * 136 + col) =
                    __floats2bfloat162_rn(acc[mt][nt][0], acc[mt][nt][1]);
                *reinterpret_cast<__nv_bfloat162*>(tp + (row0 + 8) * 136 + col) =
                    __floats2bfloat162_rn(acc[mt][nt][2], acc[mt][nt][3]);
            }
        }
        __syncthreads();

        // E/theta ladder (V_DET carries fp8-error slack)
        float E = 0.f, th = 1e30f, invb = 1.f;
#pragma unroll 1
        for (int k = 0; k < len; ++k) {
            float I = __bfloat162float(tp[(toff + k) * 136 + hh]);
            invb *= RINV;
            float cc = fmaf(CSC, I, -3.0f);
            E  = fmaf(cc, invb, E);
            th = fminf(th, fmaf(V_DET, invb, -E));
        }
        long idx = ((long)(2 * cch + q) * BATCH + b) * NHID + slab * 128 + hh;
        g_chkB[idx] = E * Afac;
        g_chkT[idx] = th;
    }
}

// ---- scanB: compose 16 sub-chunks; flags; zero out (256 CTAs) --------------
__global__ void __launch_bounds__(128) scanB_kernel(float* __restrict__ out) {
    const int b = blockIdx.x >> 2, hq = blockIdx.x & 3;
    const int h = hq * 128 + threadIdx.x;
    float v = V_RESET;
    int sp = 0;
#pragma unroll
    for (int s = 0; s < NSUB; ++s) {
        long idx = ((long)s * BATCH + b) * NHID + h;
        sp |= (v >= g_chkT[idx]);
        v = fmaf((s & 1) ? A62 : A63, v, g_chkB[idx]);
    }
    int any = __syncthreads_or(sp);
    if (threadIdx.x == 0 && any) { atomicOr(&g_bspike[b], 1); atomicOr(&g_any, 1); }
    if (hq == 0) out[b * NOUT + threadIdx.x] = 0.f;   // exact when spike-free
}

// -------- fallback bf16 GEMM (gated) + W_rec transpose -> x_proj [b][t][h] --
#define APITCH 264
#define BPITCH 72
#define SB_OFF (128 * APITCH)
#define SB_BUF (128 * BPITCH)
#define GEMM_SMEM ((SB_OFF + 2 * SB_BUF) * 2)

__global__ void __launch_bounds__(256, 2) gemm_fb_kernel(const float* __restrict__ x,
                                                         const float* __restrict__ W_in,
                                                         const float* __restrict__ W_rec) {
    if (g_any == 0) return;
    extern __shared__ __nv_bfloat16 smem2[];
    __nv_bfloat16* sA = smem2;
    __nv_bfloat16* sB = smem2 + SB_OFF;

    const int tid = threadIdx.x;
    const int warp = tid >> 5, lane = tid & 31;
    const int wm = warp & 1, wn = warp >> 1;
    const int g  = lane >> 2, tg = lane & 3;
    const int mat = lane >> 3, r8 = lane & 7;

    for (int j = blockIdx.x; j < NHID; j += 125) {
        g_wrecT[j * NHID + tid]       = W_rec[tid * NHID + j];
        g_wrecT[j * NHID + tid + 256] = W_rec[(tid + 256) * NHID + j];
    }

#pragma unroll 1
    for (int it = 0; it < 4; ++it) {
        const long tileM = ((long)blockIdx.x * 4 + it) * 128;
        __syncthreads();

#pragma unroll 4
        for (int i = 0; i < 32; ++i) {
            int idx = tid + i * 256;
            int r = idx >> 6, c4 = idx & 63;
            float4 v = *reinterpret_cast<const float4*>(x + (tileM + r) * NIN + c4 * 4);
            __nv_bfloat162 lo = __floats2bfloat162_rn(v.x, v.y);
            __nv_bfloat162 hi = __floats2bfloat162_rn(v.z, v.w);
            *reinterpret_cast<uint2*>(sA + r * APITCH + c4 * 4) =
                make_uint2(*reinterpret_cast<uint32_t*>(&lo),
                           *reinterpret_cast<uint32_t*>(&hi));
        }
#pragma unroll
        for (int i = 0; i < 4; ++i) {
            int idx = tid + i * 256;
            int r = idx >> 3, c8 = idx & 7;
            float4 a = *reinterpret_cast<const float4*>(W_in + (long)r * NIN + c8 * 8);
            float4 b2 = *reinterpret_cast<const float4*>(W_in + (long)r * NIN + c8 * 8 + 4);
            *reinterpret_cast<uint4*>(sB + r * BPITCH + c8 * 8) = cvt8_bf16(a, b2);
        }
        __syncthreads();

        const uint32_t sA32 = s2u(sA), sB32 = s2u(sB);
        uint32_t aBase[4];
#pragma unroll
        for (int mt = 0; mt < 4; ++mt)
            aBase[mt] = sA32 + (((wm * 64 + mt * 16 + (mat & 1) * 8 + r8) * APITCH)
                                + (mat >> 1) * 8) * 2;
        uint32_t bBase[2];
#pragma unroll
        for (int p2 = 0; p2 < 2; ++p2)
            bBase[p2] = (((wn * 32 + p2 * 16 + (mat >> 1) * 8 + r8) * BPITCH)
                         + (mat & 1) * 8) * 2;

        int p = 0;
#pragma unroll 1
        for (int slab = 0; slab < 4; ++slab) {
            float acc[4][4][4];
#pragma unroll
            for (int a = 0; a < 4; ++a)
#pragma unroll
                for (int b2 = 0; b2 < 4; ++b2)
#pragma unroll
                    for (int c = 0; c < 4; ++c) acc[a][b2][c] = 0.f;

#pragma unroll 1
            for (int kc = 0; kc < 4; ++kc) {
                int nkc = kc + 1, nslab = slab;
                if (nkc == 4) { nkc = 0; ++nslab; }
                const bool valid = (nslab < 4);
                uint4 br[4];
                if (valid) {
#pragma unroll
                    for (int i = 0; i < 4; ++i) {
                        int idx = tid + i * 256;
                        int r = idx >> 3, c8 = idx & 7;
                        const float* wp = W_in + (long)(nslab * 128 + r) * NIN
                                        + nkc * 64 + c8 * 8;
                        br[i] = cvt8_bf16(*reinterpret_cast<const float4*>(wp),
                                          *reinterpret_cast<const float4*>(wp + 4));
                    }
                }
                const uint32_t bufo = sB32 + p * (SB_BUF * 2);
#pragma unroll
                for (int ks = 0; ks < 4; ++ks) {
                    uint32_t af[4][4], bf[2][4];
#pragma unroll
                    for (int mt = 0; mt < 4; ++mt)
                        LDSM4(af[mt][0], af[mt][1], af[mt][2], af[mt][3],
                              aBase[mt] + (kc * 64 + ks * 16) * 2);
#pragma unroll
                    for (int p2 = 0; p2 < 2; ++p2)
                        LDSM4(bf[p2][0], bf[p2][1], bf[p2][2], bf[p2][3],
                              bufo + bBase[p2] + ks * 32);
#pragma unroll
                    for (int mt = 0; mt < 4; ++mt)
#pragma unroll
                        for (int nt = 0; nt < 4; ++nt)
                            MMA16816(acc[mt][nt],
                                     af[mt][0], af[mt][1], af[mt][2], af[mt][3],
                                     bf[nt >> 1][(nt & 1) * 2],
                                     bf[nt >> 1][(nt & 1) * 2 + 1]);
                }
                if (valid) {
#pragma unroll
                    for (int i = 0; i < 4; ++i) {
                        int idx = tid + i * 256;
                        int r = idx >> 3, c8 = idx & 7;
                        *reinterpret_cast<uint4*>(sB + (1 - p) * SB_BUF
                                                  + r * BPITCH + c8 * 8) = br[i];
                    }
                }
                __syncthreads();
                p ^= 1;
            }

#pragma unroll
            for (int mt = 0; mt < 4; ++mt) {
                long m0 = tileM + wm * 64 + mt * 16 + g;
                long b0 = m0 & 63, t0 = m0 >> 6;
                long m1 = m0 + 8;
                long b1 = m1 & 63, t1 = m1 >> 6;
                __nv_bfloat16* d0 = g_xproj + (b0 * T_STEPS + t0) * NHID;
                __nv_bfloat16* d1 = g_xproj + (b1 * T_STEPS + t1) * NHID;
#pragma unroll
                for (int nt = 0; nt < 4; ++nt) {
                    int col = slab * 128 + wn * 32 + nt * 8 + tg * 2;
                    *reinterpret_cast<__nv_bfloat162*>(d0 + col) =
                        __floats2bfloat162_rn(acc[mt][nt][0], acc[mt][nt][1]);
                    *reinterpret_cast<__nv_bfloat162*>(d1 + col) =
                        __floats2bfloat162_rn(acc[mt][nt][2], acc[mt][nt][3]);
                }
            }
        }
    }
}

// ------- fallback: full simulation + output projection (gated per batch) ----
#define PF2 8
__global__ void __launch_bounds__(128) scanfull_out_kernel(
        const float* __restrict__ W_out, float* __restrict__ out) {
    const int b = blockIdx.x;
    if (g_bspike[b] == 0) return;

    const int tid = threadIdx.x;
    __shared__ unsigned s_mask[16];
    __shared__ float sr[NHID];

    float v[4], a0[4], a1[4], psc[4], cnt[4];
#pragma unroll
    for (int i = 0; i < 4; ++i) {
        v[i] = V_RESET; a0[i] = 0.f; a1[i] = 0.f; psc[i] = 0.f; cnt[i] = 0.f;
    }
    const uint2* __restrict__ xp =
        reinterpret_cast<const uint2*>(g_xproj) + (long)b * (T_STEPS * NHID / 4) + tid;

    uint2 buf[PF2];
#pragma unroll
    for (int d = 0; d < PF2; ++d) buf[d] = xp[(long)d * (NHID / 4)];

    for (int t = 0; t < T_STEPS; t += PF2) {
#pragma unroll
        for (int d = 0; d < PF2; ++d) {
            uint2 raw = buf[d];
            int tn = t + d + PF2;
            if (tn > T_STEPS - 1) tn = T_STEPS - 1;
            buf[d] = xp[(long)tn * (NHID / 4)];

            float2 lo = __bfloat1622float2(*reinterpret_cast<__nv_bfloat162*>(&raw.x));
            float2 hi = __bfloat1622float2(*reinterpret_cast<__nv_bfloat162*>(&raw.y));
            float Ii[4] = {lo.x, lo.y, hi.x, hi.y};
            bool sp[4];
#pragma unroll
            for (int i = 0; i < 4; ++i) {
                float Itot  = Ii[i] + psc[i] + a0[i] + a1[i];
                float v_int = v[i] + DT_CM * Itot - DECAY_V * (v[i] - V_RESET);
                sp[i] = v_int >= V_TH;
                v[i]  = sp[i] ? V_RESET : v_int;
                a0[i] = a0[i] * D_ASC0 + (sp[i] ? AMP0 : 0.f);
                a1[i] = a1[i] * D_ASC1 + (sp[i] ? AMP1 : 0.f);
                cnt[i] += sp[i] ? 1.f : 0.f;
            }
            int anyl = (int)(sp[0] | sp[1] | sp[2] | sp[3]);

            if (__syncthreads_or(anyl)) {
                if (tid < 16) s_mask[tid] = 0;
                __syncthreads();
                unsigned nib = (unsigned)sp[0] | ((unsigned)sp[1] << 1)
                             | ((unsigned)sp[2] << 2) | ((unsigned)sp[3] << 3);
                if (nib) atomicOr(&s_mask[tid >> 3], nib << (4 * (tid & 7)));
                __syncthreads();
                float rec[4] = {0.f, 0.f, 0.f, 0.f};
#pragma unroll 1
                for (int w = 0; w < 16; ++w) {
                    unsigned word = s_mask[w];
                    while (word) {
                        int j = (w << 5) + __ffs(word) - 1;
                        word &= word - 1;
                        float4 wv = *reinterpret_cast<const float4*>(
                            g_wrecT + j * NHID + 4 * tid);
                        rec[0] += wv.x; rec[1] += wv.y;
                        rec[2] += wv.z; rec[3] += wv.w;
                    }
                }
                __syncthreads();
#pragma unroll
                for (int i = 0; i < 4; ++i) psc[i] = psc[i] * D_SYN + rec[i];
            } else {
#pragma unroll
                for (int i = 0; i < 4; ++i) psc[i] *= D_SYN;
            }
        }
    }

#pragma unroll
    for (int i = 0; i < 4; ++i) sr[4 * tid + i] = cnt[i] * (1.0f / T_STEPS);
    __syncthreads();

    float acc = 0.f;
    const float4* w = reinterpret_cast<const float4*>(W_out + tid * NHID);
#pragma unroll 4
    for (int i = 0; i < NHID / 4; ++i) {
        float4 wv = w[i];
        acc += wv.x * sr[4 * i] + wv.y * sr[4 * i + 1]
             + wv.z * sr[4 * i + 2] + wv.w * sr[4 * i + 3];
    }
    out[b * NOUT + tid] = acc;
}

// ---------------- launch ----------------
extern "C" void kernel_launch(void* const* d_in, const int* in_sizes, int n_in,
                              void* d_out, int out_size) {
    const float* x     = (const float*)d_in[0];
    const float* W_in  = (const float*)d_in[1];
    const float* W_rec = (const float*)d_in[2];
    const float* W_out = (const float*)d_in[3];
    float* out = (float*)d_out;
    (void)in_sizes; (void)n_in; (void)out_size;

    prep_kernel<<<65, 256>>>(W_in);
    cvt_x8_kernel<<<2048, 256>>>(x);

    cudaFuncSetAttribute(fused_kernel,
                         cudaFuncAttributeMaxDynamicSharedMemorySize, FUSED_SMEM);
    fused_kernel<<<8 * BATCH, 256, FUSED_SMEM>>>();

    scanB_kernel<<<4 * BATCH, 128>>>(out);

    cudaFuncSetAttribute(gemm_fb_kernel,
                         cudaFuncAttributeMaxDynamicSharedMemorySize, GEMM_SMEM);
    gemm_fb_kernel<<<125, 256, GEMM_SMEM>>>(x, W_in, W_rec);

    scanfull_out_kernel<<<BATCH, NOUT>>>(W_out, out);
}

// round 16
// speedup vs baseline: 1.1193x; 1.1193x over previous
#include <cuda_runtime.h>
#include <cuda_bf16.h>
#include <cstdint>

#define T_STEPS 1000
#define BATCH   64
#define NIN     256
#define NHID    512
#define NOUT    128
#define M_ROWS  (T_STEPS * BATCH)

#define V_TH     (-45.0f)
#define V_DET    (-48.5f)    // detection threshold with fp8-error slack
#define V_RESET  (-60.0f)
#define DT_CM    (0.5f)
#define DECAY_V  (0.05f)
#define D_ASC0   (0.9048374180359595f)
#define D_ASC1   (0.8187307530779818f)
#define D_SYN    (0.8187307530779818f)
#define AMP0     (1.0f)
#define AMP1     (-2.0f)

#define RINV     (1.0526315789473684f)   // 0.95^-1
#define A63      (0.0394991161f)         // 0.95^63
#define A62      (0.0415780170f)         // 0.95^62
#define NSUB     16
#define CSC      (0.00390625f)           // 0.5 / (4*32) fp8 scale compensation

__device__ __align__(128) __nv_bfloat16 g_xproj[(size_t)M_ROWS * NHID]; // fallback only
__device__ __align__(128) uint32_t g_w8[NHID * NIN / 4];                // e4m3 W, FRAGMENT order
__device__ __align__(128) float g_wrecT[NHID * NHID];                   // built by fallback
__device__ __align__(128) float g_chkB[NSUB * BATCH * NHID];
__device__ __align__(128) float g_chkT[NSUB * BATCH * NHID];
__device__ int g_bspike[BATCH];
__device__ int g_any;

static __device__ __forceinline__ uint32_t s2u(const void* p) {
    return (uint32_t)__cvta_generic_to_shared(p);
}
static __device__ __forceinline__ uint32_t pack_e4m3_4(float v0, float v1, float v2, float v3) {
    uint16_t lo, hi;   // cvt packs: low byte = 2nd operand
    asm("cvt.rn.satfinite.e4m3x2.f32 %0, %1, %2;" : "=h"(lo) : "f"(v1), "f"(v0));
    asm("cvt.rn.satfinite.e4m3x2.f32 %0, %1, %2;" : "=h"(hi) : "f"(v3), "f"(v2));
    return (uint32_t)lo | ((uint32_t)hi << 16);
}
static __device__ __forceinline__ uint4 cvt8_bf16(float4 a, float4 b) {
    __nv_bfloat162 p0 = __floats2bfloat162_rn(a.x, a.y);
    __nv_bfloat162 p1 = __floats2bfloat162_rn(a.z, a.w);
    __nv_bfloat162 p2 = __floats2bfloat162_rn(b.x, b.y);
    __nv_bfloat162 p3 = __floats2bfloat162_rn(b.z, b.w);
    return make_uint4(*reinterpret_cast<uint32_t*>(&p0), *reinterpret_cast<uint32_t*>(&p1),
                      *reinterpret_cast<uint32_t*>(&p2), *reinterpret_cast<uint32_t*>(&p3));
}
#define LDSM4(d0, d1, d2, d3, a)                                                 \
    asm volatile("ldmatrix.sync.aligned.m8n8.x4.shared.b16 {%0,%1,%2,%3}, [%4];" \
                 : "=r"(d0), "=r"(d1), "=r"(d2), "=r"(d3) : "r"(a))
#define MMA16816(ac, a0, a1, a2, a3, b0, b1)                                     \
    asm volatile("mma.sync.aligned.m16n8k16.row.col.f32.bf16.bf16.f32 "          \
                 "{%0,%1,%2,%3}, {%4,%5,%6,%7}, {%8,%9}, {%0,%1,%2,%3};\n"       \
                 : "+f"(ac[0]), "+f"(ac[1]), "+f"(ac[2]), "+f"(ac[3])            \
                 : "r"(a0), "r"(a1), "r"(a2), "r"(a3), "r"(b0), "r"(b1))
#define MMAFP8(ac, a0, a1, a2, a3, b0, b1)                                       \
    asm volatile("mma.sync.aligned.m16n8k32.row.col.f32.e4m3.e4m3.f32 "          \
                 "{%0,%1,%2,%3}, {%4,%5,%6,%7}, {%8,%9}, {%0,%1,%2,%3};\n"       \
                 : "+f"(ac[0]), "+f"(ac[1]), "+f"(ac[2]), "+f"(ac[3])            \
                 : "r"(a0), "r"(a1), "r"(a2), "r"(a3), "r"(b0), "r"(b1))

// ---- prep: e4m3 fragment-pack + flag resets (65 CTAs) ----------------------
__global__ void __launch_bounds__(256) prep_kernel(const float* __restrict__ W_in) {
    const int bid = blockIdx.x, tid = threadIdx.x;
    if (bid == 64) {
        if (tid < BATCH) g_bspike[tid] = 0;
        if (tid == BATCH) g_any = 0;
        return;
    }
    int uu = bid * 256 + tid;                    // < 16384
    int nt8 = uu >> 8, ks = (uu >> 5) & 7, lane = uu & 31;
    int gg = lane >> 2, tg = lane & 3;
    int n = nt8 * 8 + gg;
    int k0 = ks * 32 + tg * 4;
    float4 w0 = *reinterpret_cast<const float4*>(W_in + n * NIN + k0);
    float4 w1 = *reinterpret_cast<const float4*>(W_in + n * NIN + k0 + 16);
    uint2 pk;
    pk.x = pack_e4m3_4(32.f * w0.x, 32.f * w0.y, 32.f * w0.z, 32.f * w0.w);
    pk.y = pack_e4m3_4(32.f * w1.x, 32.f * w1.y, 32.f * w1.z, 32.f * w1.w);
    *reinterpret_cast<uint2*>(reinterpret_cast<char*>(g_w8) + (size_t)uu * 8) = pk;
}

// ---------------- fused FP8 GEMM + chunk-summary scan (R12/R14 validated) ---
// CTA = (b, 125-t chunk), 256 threads / 8 warps (2m x 4n, warp tile 64x32).
// A in fragment order (e4m3 x4); B single buffer; smem 100.4KB -> 2 CTAs/SM.
// R16 change: ladder unrolled x7 (fixed 63-trip, predicated tail).
#define SM_A   0            // 32768
#define SM_B   32768        // 32768
#define SM_TP  65536        // 128 x 136 bf16 = 34816
#define FUSED_SMEM 100352

__global__ void __launch_bounds__(256, 2) fused_kernel(const float* __restrict__ x) {
    extern __shared__ char smem[];
    const int tid = threadIdx.x, warp = tid >> 5, lane = tid & 31;
    const int b = blockIdx.x & 63, cch = blockIdx.x >> 6;   // chunk 0..7
    const int t0 = cch * 125;
    const int wm = warp & 1, wn = warp >> 1;                // 2m x 4n warps
    const int gg = lane >> 2, tg = lane & 3;

    // ---- stage A in fragment order: 8 units (16B) per thread ----
#pragma unroll
    for (int i = 0; i < 8; ++i) {
        int u = tid + i * 256;                   // (mtile*8+ks)*32 + lane_u
        int mtile = u >> 8, ks = (u >> 5) & 7, lu = u & 31;
        int ug = lu >> 2, utg = lu & 3;
        int r0 = mtile * 16 + ug, r1 = r0 + 8;   // r0 <= 119 always valid
        int k0 = ks * 32 + utg * 4;
        const float* x0 = x + ((long)(t0 + r0) * 64 + b) * NIN;
        float4 q0 = *reinterpret_cast<const float4*>(x0 + k0);
        float4 q2 = *reinterpret_cast<const float4*>(x0 + k0 + 16);
        float4 q1 = make_float4(0.f, 0.f, 0.f, 0.f), q3 = q1;
        if (r1 < 125) {
            const float* x1 = x + ((long)(t0 + r1) * 64 + b) * NIN;
            q1 = *reinterpret_cast<const float4*>(x1 + k0);
            q3 = *reinterpret_cast<const float4*>(x1 + k0 + 16);
        }
        uint4 frag;
        frag.x = pack_e4m3_4(4.f * q0.x, 4.f * q0.y, 4.f * q0.z, 4.f * q0.w); // a0
        frag.y = pack_e4m3_4(4.f * q1.x, 4.f * q1.y, 4.f * q1.z, 4.f * q1.w); // a1
        frag.z = pack_e4m3_4(4.f * q2.x, 4.f * q2.y, 4.f * q2.z, 4.f * q2.w); // a2
        frag.w = pack_e4m3_4(4.f * q3.x, 4.f * q3.y, 4.f * q3.z, 4.f * q3.w); // a3
        *reinterpret_cast<uint4*>(smem + SM_A + (size_t)u * 16) = frag;
    }

    const uint32_t sA32 = s2u(smem + SM_A);
    const uint32_t sB32 = s2u(smem + SM_B);
    __nv_bfloat16* tp = reinterpret_cast<__nv_bfloat16*>(smem + SM_TP);

    const int q  = tid >> 7, hh = tid & 127;     // half-split ladder
    const int toff = q ? 63 : 0;
    const int len  = q ? 62 : 63;
    const float Afac = q ? A62 : A63;

#pragma unroll 1
    for (int slab = 0; slab < 4; ++slab) {
        __syncthreads();
#pragma unroll
        for (int i = 0; i < 8; ++i) {
            int idx = tid + i * 256;    // uint4 units, 2048 total
            uint4 v = reinterpret_cast<const uint4*>(g_w8)[slab * 2048 + idx];
            *reinterpret_cast<uint4*>(smem + SM_B + (size_t)idx * 16) = v;
        }
        __syncthreads();

        float acc[4][4][4];
#pragma unroll
        for (int a = 0; a < 4; ++a)
#pragma unroll
            for (int b2 = 0; b2 < 4; ++b2)
#pragma unroll
                for (int c = 0; c < 4; ++c) acc[a][b2][c] = 0.f;

#pragma unroll
        for (int ks = 0; ks < 8; ++ks) {
            uint4 af[4];
            uint2 bf[4];
#pragma unroll
            for (int mt = 0; mt < 4; ++mt) {
                uint32_t addr = sA32 + (((wm * 4 + mt) * 8 + ks) * 32 + lane) * 16;
                asm volatile("ld.shared.v4.u32 {%0,%1,%2,%3}, [%4];"
                             : "=r"(af[mt].x), "=r"(af[mt].y),
                               "=r"(af[mt].z), "=r"(af[mt].w) : "r"(addr));
            }
#pragma unroll
            for (int nt = 0; nt < 4; ++nt) {
                uint32_t addr = sB32 + (((wn * 4 + nt) * 8 + ks) * 32 + lane) * 8;
                asm volatile("ld.shared.v2.u32 {%0,%1}, [%2];"
                             : "=r"(bf[nt].x), "=r"(bf[nt].y) : "r"(addr));
            }
#pragma unroll
            for (int mt = 0; mt < 4; ++mt)
#pragma unroll
                for (int nt = 0; nt < 4; ++nt)
                    MMAFP8(acc[mt][nt], af[mt].x, af[mt].y, af[mt].z, af[mt].w,
                           bf[nt].x, bf[nt].y);
        }

        // transpose acc -> tp[t][h'] (prior ladder finished at stage-B sync)
#pragma unroll
        for (int mt = 0; mt < 4; ++mt) {
            int row0 = wm * 64 + mt * 16 + gg;
#pragma unroll
            for (int nt = 0; nt < 4; ++nt) {
                int col = wn * 32 + nt * 8 + tg * 2;
                *reinterpret_cast<__nv_bfloat162*>(tp + row0 * 136 + col) =
                    __floats2bfloat162_rn(acc[mt][nt][0], acc[mt][nt][1]);
                *reinterpret_cast<__nv_bfloat162*>(tp + (row0 + 8) * 136 + col) =
                    __floats2bfloat162_rn(acc[mt][nt][2], acc[mt][nt][3]);
            }
        }
        __syncthreads();

        // E/theta ladder, unrolled x7 (fixed 63 trips; tail predicated).
        // q=1 tail reads rows 126 (in-bounds, values unused).
        float E = 0.f, th = 1e30f, invb = 1.f;
#pragma unroll 7
        for (int k = 0; k < 63; ++k) {
            float I = __bfloat162float(tp[(toff + k) * 136 + hh]);
            invb *= RINV;
            if (k < len) {
                float cc = fmaf(CSC, I, -3.0f);
                E  = fmaf(cc, invb, E);
                th = fminf(th, fmaf(V_DET, invb, -E));
            }
        }
        long idx = ((long)(2 * cch + q) * BATCH + b) * NHID + slab * 128 + hh;
        g_chkB[idx] = E * Afac;
        g_chkT[idx] = th;
    }
}

// ---- scanB: compose 16 sub-chunks; flags; zero out (256 CTAs) --------------
__global__ void __launch_bounds__(128) scanB_kernel(float* __restrict__ out) {
    const int b = blockIdx.x >> 2, hq = blockIdx.x & 3;
    const int h = hq * 128 + threadIdx.x;
    float v = V_RESET;
    int sp = 0;
#pragma unroll
    for (int s = 0; s < NSUB; ++s) {
        long idx = ((long)s * BATCH + b) * NHID + h;
        sp |= (v >= g_chkT[idx]);
        v = fmaf((s & 1) ? A62 : A63, v, g_chkB[idx]);
    }
    int any = __syncthreads_or(sp);
    if (threadIdx.x == 0 && any) { atomicOr(&g_bspike[b], 1); atomicOr(&g_any, 1); }
    if (hq == 0) out[b * NOUT + threadIdx.x] = 0.f;   // exact when spike-free
}

// -------- fallback bf16 GEMM (gated) + W_rec transpose -> x_proj [b][t][h] --
#define APITCH 264
#define BPITCH 72
#define SB_OFF (128 * APITCH)
#define SB_BUF (128 * BPITCH)
#define GEMM_SMEM ((SB_OFF + 2 * SB_BUF) * 2)

__global__ void __launch_bounds__(256, 2) gemm_fb_kernel(const float* __restrict__ x,
                                                         const float* __restrict__ W_in,
                                                         const float* __restrict__ W_rec) {
    if (g_any == 0) return;
    extern __shared__ __nv_bfloat16 smem2[];
    __nv_bfloat16* sA = smem2;
    __nv_bfloat16* sB = smem2 + SB_OFF;

    const int tid = threadIdx.x;
    const int warp = tid >> 5, lane = tid & 31;
    const int wm = warp & 1, wn = warp >> 1;
    const int g  = lane >> 2, tg = lane & 3;
    const int mat = lane >> 3, r8 = lane & 7;

    for (int j = blockIdx.x; j < NHID; j += 125) {
        g_wrecT[j * NHID + tid]       = W_rec[tid * NHID + j];
        g_wrecT[j * NHID + tid + 256] = W_rec[(tid + 256) * NHID + j];
    }

#pragma unroll 1
    for (int it = 0; it < 4; ++it) {
        const long tileM = ((long)blockIdx.x * 4 + it) * 128;
        __syncthreads();

#pragma unroll 4
        for (int i = 0; i < 32; ++i) {
            int idx = tid + i * 256;
            int r = idx >> 6, c4 = idx & 63;
            float4 v = *reinterpret_cast<const float4*>(x + (tileM + r) * NIN + c4 * 4);
            __nv_bfloat162 lo = __floats2bfloat162_rn(v.x, v.y);
            __nv_bfloat162 hi = __floats2bfloat162_rn(v.z, v.w);
            *reinterpret_cast<uint2*>(sA + r * APITCH + c4 * 4) =
                make_uint2(*reinterpret_cast<uint32_t*>(&lo),
                           *reinterpret_cast<uint32_t*>(&hi));
        }
#pragma unroll
        for (int i = 0; i < 4; ++i) {
            int idx = tid + i * 256;
            int r = idx >> 3, c8 = idx & 7;
            float4 a = *reinterpret_cast<const float4*>(W_in + (long)r * NIN + c8 * 8);
            float4 b2 = *reinterpret_cast<const float4*>(W_in + (long)r * NIN + c8 * 8 + 4);
            *reinterpret_cast<uint4*>(sB + r * BPITCH + c8 * 8) = cvt8_bf16(a, b2);
        }
        __syncthreads();

        const uint32_t sA32 = s2u(sA), sB32 = s2u(sB);
        uint32_t aBase[4];
#pragma unroll
        for (int mt = 0; mt < 4; ++mt)
            aBase[mt] = sA32 + (((wm * 64 + mt * 16 + (mat & 1) * 8 + r8) * APITCH)
                                + (mat >> 1) * 8) * 2;
        uint32_t bBase[2];
#pragma unroll
        for (int p2 = 0; p2 < 2; ++p2)
            bBase[p2] = (((wn * 32 + p2 * 16 + (mat >> 1) * 8 + r8) * BPITCH)
                         + (mat & 1) * 8) * 2;

        int p = 0;
#pragma unroll 1
        for (int slab = 0; slab < 4; ++slab) {
            float acc[4][4][4];
#pragma unroll
            for (int a = 0; a < 4; ++a)
#pragma unroll
                for (int b2 = 0; b2 < 4; ++b2)
#pragma unroll
                    for (int c = 0; c < 4; ++c) acc[a][b2][c] = 0.f;

#pragma unroll 1
            for (int kc = 0; kc < 4; ++kc) {
                int nkc = kc + 1, nslab = slab;
                if (nkc == 4) { nkc = 0; ++nslab; }
                const bool valid = (nslab < 4);
                uint4 br[4];
                if (valid) {
#pragma unroll
                    for (int i = 0; i < 4; ++i) {
                        int idx = tid + i * 256;
                        int r = idx >> 3, c8 = idx & 7;
                        const float* wp = W_in + (long)(nslab * 128 + r) * NIN
                                        + nkc * 64 + c8 * 8;
                        br[i] = cvt8_bf16(*reinterpret_cast<const float4*>(wp),
                                          *reinterpret_cast<const float4*>(wp + 4));
                    }
                }
                const uint32_t bufo = sB32 + p * (SB_BUF * 2);
#pragma unroll
                for (int ks = 0; ks < 4; ++ks) {
                    uint32_t af[4][4], bf[2][4];
#pragma unroll
                    for (int mt = 0; mt < 4; ++mt)
                        LDSM4(af[mt][0], af[mt][1], af[mt][2], af[mt][3],
                              aBase[mt] + (kc * 64 + ks * 16) * 2);
#pragma unroll
                    for (int p2 = 0; p2 < 2; ++p2)
                        LDSM4(bf[p2][0], bf[p2][1], bf[p2][2], bf[p2][3],
                              bufo + bBase[p2] + ks * 32);
#pragma unroll
                    for (int mt = 0; mt < 4; ++mt)
#pragma unroll
                        for (int nt = 0; nt < 4; ++nt)
                            MMA16816(acc[mt][nt],
                                     af[mt][0], af[mt][1], af[mt][2], af[mt][3],
                                     bf[nt >> 1][(nt & 1) * 2],
                                     bf[nt >> 1][(nt & 1) * 2 + 1]);
                }
                if (valid) {
#pragma unroll
                    for (int i = 0; i < 4; ++i) {
                        int idx = tid + i * 256;
                        int r = idx >> 3, c8 = idx & 7;
                        *reinterpret_cast<uint4*>(sB + (1 - p) * SB_BUF
                                                  + r * BPITCH + c8 * 8) = br[i];
                    }
                }
                __syncthreads();
                p ^= 1;
            }

#pragma unroll
            for (int mt = 0; mt < 4; ++mt) {
                long m0 = tileM + wm * 64 + mt * 16 + g;
                long b0 = m0 & 63, t0 = m0 >> 6;
                long m1 = m0 + 8;
                long b1 = m1 & 63, t1 = m1 >> 6;
                __nv_bfloat16* d0 = g_xproj + (b0 * T_STEPS + t0) * NHID;
                __nv_bfloat16* d1 = g_xproj + (b1 * T_STEPS + t1) * NHID;
#pragma unroll
                for (int nt = 0; nt < 4; ++nt) {
                    int col = slab * 128 + wn * 32 + nt * 8 + tg * 2;
                    *reinterpret_cast<__nv_bfloat162*>(d0 + col) =
                        __floats2bfloat162_rn(acc[mt][nt][0], acc[mt][nt][1]);
                    *reinterpret_cast<__nv_bfloat162*>(d1 + col) =
                        __floats2bfloat162_rn(acc[mt][nt][2], acc[mt][nt][3]);
                }
            }
        }
    }
}

// ------- fallback: full simulation + output projection (gated per batch) ----
#define PF2 8
__global__ void __launch_bounds__(128) scanfull_out_kernel(
        const float* __restrict__ W_out, float* __restrict__ out) {
    const int b = blockIdx.x;
    if (g_bspike[b] == 0) return;

    const int tid = threadIdx.x;
    __shared__ unsigned s_mask[16];
    __shared__ float sr[NHID];

    float v[4], a0[4], a1[4], psc[4], cnt[4];
#pragma unroll
    for (int i = 0; i < 4; ++i) {
        v[i] = V_RESET; a0[i] = 0.f; a1[i] = 0.f; psc[i] = 0.f; cnt[i] = 0.f;
    }
    const uint2* __restrict__ xp =
        reinterpret_cast<const uint2*>(g_xproj) + (long)b * (T_STEPS * NHID / 4) + tid;

    uint2 buf[PF2];
#pragma unroll
    for (int d = 0; d < PF2; ++d) buf[d] = xp[(long)d * (NHID / 4)];

    for (int t = 0; t < T_STEPS; t += PF2) {
#pragma unroll
        for (int d = 0; d < PF2; ++d) {
            uint2 raw = buf[d];
            int tn = t + d + PF2;
            if (tn > T_STEPS - 1) tn = T_STEPS - 1;
            buf[d] = xp[(long)tn * (NHID / 4)];

            float2 lo = __bfloat1622float2(*reinterpret_cast<__nv_bfloat162*>(&raw.x));
            float2 hi = __bfloat1622float2(*reinterpret_cast<__nv_bfloat162*>(&raw.y));
            float Ii[4] = {lo.x, lo.y, hi.x, hi.y};
            bool sp[4];
#pragma unroll
            for (int i = 0; i < 4; ++i) {
                float Itot  = Ii[i] + psc[i] + a0[i] + a1[i];
                float v_int = v[i] + DT_CM * Itot - DECAY_V * (v[i] - V_RESET);
                sp[i] = v_int >= V_TH;
                v[i]  = sp[i] ? V_RESET : v_int;
                a0[i] = a0[i] * D_ASC0 + (sp[i] ? AMP0 : 0.f);
                a1[i] = a1[i] * D_ASC1 + (sp[i] ? AMP1 : 0.f);
                cnt[i] += sp[i] ? 1.f : 0.f;
            }
            int anyl = (int)(sp[0] | sp[1] | sp[2] | sp[3]);

            if (__syncthreads_or(anyl)) {
                if (tid < 16) s_mask[tid] = 0;
                __syncthreads();
                unsigned nib = (unsigned)sp[0] | ((unsigned)sp[1] << 1)
                             | ((unsigned)sp[2] << 2) | ((unsigned)sp[3] << 3);
                if (nib) atomicOr(&s_mask[tid >> 3], nib << (4 * (tid & 7)));
                __syncthreads();
                float rec[4] = {0.f, 0.f, 0.f, 0.f};
#pragma unroll 1
                for (int w = 0; w < 16; ++w) {
                    unsigned word = s_mask[w];
                    while (word) {
                        int j = (w << 5) + __ffs(word) - 1;
                        word &= word - 1;
                        float4 wv = *reinterpret_cast<const float4*>(
                            g_wrecT + j * NHID + 4 * tid);
                        rec[0] += wv.x; rec[1] += wv.y;
                        rec[2] += wv.z; rec[3] += wv.w;
                    }
                }
                __syncthreads();
#pragma unroll
                for (int i = 0; i < 4; ++i) psc[i] = psc[i] * D_SYN + rec[i];
            } else {
#pragma unroll
                for (int i = 0; i < 4; ++i) psc[i] *= D_SYN;
            }
        }
    }

#pragma unroll
    for (int i = 0; i < 4; ++i) sr[4 * tid + i] = cnt[i] * (1.0f / T_STEPS);
    __syncthreads();

    float acc = 0.f;
    const float4* w = reinterpret_cast<const float4*>(W_out + tid * NHID);
#pragma unroll 4
    for (int i = 0; i < NHID / 4; ++i) {
        float4 wv = w[i];
        acc += wv.x * sr[4 * i] + wv.y * sr[4 * i + 1]
             + wv.z * sr[4 * i + 2] + wv.w * sr[4 * i + 3];
    }
    out[b * NOUT + tid] = acc;
}

// ---------------- launch ----------------
extern "C" void kernel_launch(void* const* d_in, const int* in_sizes, int n_in,
                              void* d_out, int out_size) {
    const float* x     = (const float*)d_in[0];
    const float* W_in  = (const float*)d_in[1];
    const float* W_rec = (const float*)d_in[2];
    const float* W_out = (const float*)d_in[3];
    float* out = (float*)d_out;
    (void)in_sizes; (void)n_in; (void)out_size;

    prep_kernel<<<65, 256>>>(W_in);

    cudaFuncSetAttribute(fused_kernel,
                         cudaFuncAttributeMaxDynamicSharedMemorySize, FUSED_SMEM);
    fused_kernel<<<8 * BATCH, 256, FUSED_SMEM>>>(x);

    scanB_kernel<<<4 * BATCH, 128>>>(out);

    cudaFuncSetAttribute(gemm_fb_kernel,
                         cudaFuncAttributeMaxDynamicSharedMemorySize, GEMM_SMEM);
    gemm_fb_kernel<<<125, 256, GEMM_SMEM>>>(x, W_in, W_rec);

    scanfull_out_kernel<<<BATCH, NOUT>>>(W_out, out);
}

// round 17
// speedup vs baseline: 1.1374x; 1.0162x over previous
#include <cuda_runtime.h>
#include <cuda_bf16.h>
#include <cstdint>

#define T_STEPS 1000
#define BATCH   64
#define NIN     256
#define NHID    512
#define NOUT    128
#define M_ROWS  (T_STEPS * BATCH)

#define V_TH     (-45.0f)
#define V_DET    (-48.5f)    // detection threshold with fp8-error slack
#define V_RESET  (-60.0f)
#define DT_CM    (0.5f)
#define DECAY_V  (0.05f)
#define D_ASC0   (0.9048374180359595f)
#define D_ASC1   (0.8187307530779818f)
#define D_SYN    (0.8187307530779818f)
#define AMP0     (1.0f)
#define AMP1     (-2.0f)

#define RINV     (1.0526315789473684f)   // 0.95^-1
#define A63      (0.0394991161f)         // 0.95^63
#define A62      (0.0415780170f)         // 0.95^62
#define NSUB     16
#define CSC      (0.00390625f)           // 0.5 / (4*32) fp8 scale compensation

__device__ __align__(128) __nv_bfloat16 g_xproj[(size_t)M_ROWS * NHID]; // fallback only
__device__ __align__(128) uint32_t g_w8[NHID * NIN / 4];                // e4m3 W, FRAGMENT order
__device__ __align__(128) float g_wrecT[NHID * NHID];                   // built by fallback
__device__ __align__(128) float g_chkB[NSUB * BATCH * NHID];
__device__ __align__(128) float g_chkT[NSUB * BATCH * NHID];
__device__ int g_bspike[BATCH];
__device__ int g_cnt[BATCH];
__device__ int g_any;

static __device__ __forceinline__ uint32_t s2u(const void* p) {
    return (uint32_t)__cvta_generic_to_shared(p);
}
static __device__ __forceinline__ uint32_t pack_e4m3_4(float v0, float v1, float v2, float v3) {
    uint16_t lo, hi;   // cvt packs: low byte = 2nd operand
    asm("cvt.rn.satfinite.e4m3x2.f32 %0, %1, %2;" : "=h"(lo) : "f"(v1), "f"(v0));
    asm("cvt.rn.satfinite.e4m3x2.f32 %0, %1, %2;" : "=h"(hi) : "f"(v3), "f"(v2));
    return (uint32_t)lo | ((uint32_t)hi << 16);
}
static __device__ __forceinline__ uint4 cvt8_bf16(float4 a, float4 b) {
    __nv_bfloat162 p0 = __floats2bfloat162_rn(a.x, a.y);
    __nv_bfloat162 p1 = __floats2bfloat162_rn(a.z, a.w);
    __nv_bfloat162 p2 = __floats2bfloat162_rn(b.x, b.y);
    __nv_bfloat162 p3 = __floats2bfloat162_rn(b.z, b.w);
    return make_uint4(*reinterpret_cast<uint32_t*>(&p0), *reinterpret_cast<uint32_t*>(&p1),
                      *reinterpret_cast<uint32_t*>(&p2), *reinterpret_cast<uint32_t*>(&p3));
}
#define LDSM4(d0, d1, d2, d3, a)                                                 \
    asm volatile("ldmatrix.sync.aligned.m8n8.x4.shared.b16 {%0,%1,%2,%3}, [%4];" \
                 : "=r"(d0), "=r"(d1), "=r"(d2), "=r"(d3) : "r"(a))
#define MMA16816(ac, a0, a1, a2, a3, b0, b1)                                     \
    asm volatile("mma.sync.aligned.m16n8k16.row.col.f32.bf16.bf16.f32 "          \
                 "{%0,%1,%2,%3}, {%4,%5,%6,%7}, {%8,%9}, {%0,%1,%2,%3};\n"       \
                 : "+f"(ac[0]), "+f"(ac[1]), "+f"(ac[2]), "+f"(ac[3])            \
                 : "r"(a0), "r"(a1), "r"(a2), "r"(a3), "r"(b0), "r"(b1))
#define MMAFP8(ac, a0, a1, a2, a3, b0, b1)                                       \
    asm volatile("mma.sync.aligned.m16n8k32.row.col.f32.e4m3.e4m3.f32 "          \
                 "{%0,%1,%2,%3}, {%4,%5,%6,%7}, {%8,%9}, {%0,%1,%2,%3};\n"       \
                 : "+f"(ac[0]), "+f"(ac[1]), "+f"(ac[2]), "+f"(ac[3])            \
                 : "r"(a0), "r"(a1), "r"(a2), "r"(a3), "r"(b0), "r"(b1))

// ---- prep: e4m3 fragment-pack + flag/counter resets (65 CTAs) --------------
__global__ void __launch_bounds__(256) prep_kernel(const float* __restrict__ W_in) {
    const int bid = blockIdx.x, tid = threadIdx.x;
    if (bid == 64) {
        if (tid < BATCH) { g_bspike[tid] = 0; g_cnt[tid] = 0; }
        if (tid == BATCH) g_any = 0;
        return;
    }
    int uu = bid * 256 + tid;                    // < 16384
    int nt8 = uu >> 8, ks = (uu >> 5) & 7, lane = uu & 31;
    int gg = lane >> 2, tg = lane & 3;
    int n = nt8 * 8 + gg;
    int k0 = ks * 32 + tg * 4;
    float4 w0 = *reinterpret_cast<const float4*>(W_in + n * NIN + k0);
    float4 w1 = *reinterpret_cast<const float4*>(W_in + n * NIN + k0 + 16);
    uint2 pk;
    pk.x = pack_e4m3_4(32.f * w0.x, 32.f * w0.y, 32.f * w0.z, 32.f * w0.w);
    pk.y = pack_e4m3_4(32.f * w1.x, 32.f * w1.y, 32.f * w1.z, 32.f * w1.w);
    *reinterpret_cast<uint2*>(reinterpret_cast<char*>(g_w8) + (size_t)uu * 8) = pk;
}

// ---------------- fused FP8 GEMM + chunk scan + inline composition ----------
// CTA = (b, 125-t chunk), 256 threads / 8 warps (2m x 4n, warp tile 64x32).
// Last-finishing CTA per batch composes the 16 sub-chunks (threadfence pattern).
#define SM_A   0            // 32768
#define SM_B   32768        // 32768
#define SM_TP  65536        // 128 x 136 bf16 = 34816
#define FUSED_SMEM 100352

__global__ void __launch_bounds__(256, 2) fused_kernel(const float* __restrict__ x,
                                                       float* __restrict__ out) {
    extern __shared__ char smem[];
    const int tid = threadIdx.x, warp = tid >> 5, lane = tid & 31;
    const int b = blockIdx.x & 63, cch = blockIdx.x >> 6;   // chunk 0..7
    const int t0 = cch * 125;
    const int wm = warp & 1, wn = warp >> 1;                // 2m x 4n warps
    const int gg = lane >> 2, tg = lane & 3;

    // ---- stage A in fragment order: 8 units (16B) per thread ----
#pragma unroll
    for (int i = 0; i < 8; ++i) {
        int u = tid + i * 256;                   // (mtile*8+ks)*32 + lane_u
        int mtile = u >> 8, ks = (u >> 5) & 7, lu = u & 31;
        int ug = lu >> 2, utg = lu & 3;
        int r0 = mtile * 16 + ug, r1 = r0 + 8;   // r0 <= 119 always valid
        int k0 = ks * 32 + utg * 4;
        const float* x0 = x + ((long)(t0 + r0) * 64 + b) * NIN;
        float4 q0 = *reinterpret_cast<const float4*>(x0 + k0);
        float4 q2 = *reinterpret_cast<const float4*>(x0 + k0 + 16);
        float4 q1 = make_float4(0.f, 0.f, 0.f, 0.f), q3 = q1;
        if (r1 < 125) {
            const float* x1 = x + ((long)(t0 + r1) * 64 + b) * NIN;
            q1 = *reinterpret_cast<const float4*>(x1 + k0);
            q3 = *reinterpret_cast<const float4*>(x1 + k0 + 16);
        }
        uint4 frag;
        frag.x = pack_e4m3_4(4.f * q0.x, 4.f * q0.y, 4.f * q0.z, 4.f * q0.w); // a0
        frag.y = pack_e4m3_4(4.f * q1.x, 4.f * q1.y, 4.f * q1.z, 4.f * q1.w); // a1
        frag.z = pack_e4m3_4(4.f * q2.x, 4.f * q2.y, 4.f * q2.z, 4.f * q2.w); // a2
        frag.w = pack_e4m3_4(4.f * q3.x, 4.f * q3.y, 4.f * q3.z, 4.f * q3.w); // a3
        *reinterpret_cast<uint4*>(smem + SM_A + (size_t)u * 16) = frag;
    }

    const uint32_t sA32 = s2u(smem + SM_A);
    const uint32_t sB32 = s2u(smem + SM_B);
    __nv_bfloat16* tp = reinterpret_cast<__nv_bfloat16*>(smem + SM_TP);

    const int q  = tid >> 7, hh = tid & 127;     // half-split ladder
    const int toff = q ? 63 : 0;
    const int len  = q ? 62 : 63;
    const float Afac = q ? A62 : A63;

#pragma unroll 1
    for (int slab = 0; slab < 4; ++slab) {
        __syncthreads();
#pragma unroll
        for (int i = 0; i < 8; ++i) {
            int idx = tid + i * 256;    // uint4 units, 2048 total
            uint4 v = reinterpret_cast<const uint4*>(g_w8)[slab * 2048 + idx];
            *reinterpret_cast<uint4*>(smem + SM_B + (size_t)idx * 16) = v;
        }
        __syncthreads();

        float acc[4][4][4];
#pragma unroll
        for (int a = 0; a < 4; ++a)
#pragma unroll
            for (int b2 = 0; b2 < 4; ++b2)
#pragma unroll
                for (int c = 0; c < 4; ++c) acc[a][b2][c] = 0.f;

#pragma unroll
        for (int ks = 0; ks < 8; ++ks) {
            uint4 af[4];
            uint2 bf[4];
#pragma unroll
            for (int mt = 0; mt < 4; ++mt) {
                uint32_t addr = sA32 + (((wm * 4 + mt) * 8 + ks) * 32 + lane) * 16;
                asm volatile("ld.shared.v4.u32 {%0,%1,%2,%3}, [%4];"
                             : "=r"(af[mt].x), "=r"(af[mt].y),
                               "=r"(af[mt].z), "=r"(af[mt].w) : "r"(addr));
            }
#pragma unroll
            for (int nt = 0; nt < 4; ++nt) {
                uint32_t addr = sB32 + (((wn * 4 + nt) * 8 + ks) * 32 + lane) * 8;
                asm volatile("ld.shared.v2.u32 {%0,%1}, [%2];"
                             : "=r"(bf[nt].x), "=r"(bf[nt].y) : "r"(addr));
            }
#pragma unroll
            for (int mt = 0; mt < 4; ++mt)
#pragma unroll
                for (int nt = 0; nt < 4; ++nt)
                    MMAFP8(acc[mt][nt], af[mt].x, af[mt].y, af[mt].z, af[mt].w,
                           bf[nt].x, bf[nt].y);
        }

        // transpose acc -> tp[t][h'] (prior ladder finished at stage-B sync)
#pragma unroll
        for (int mt = 0; mt < 4; ++mt) {
            int row0 = wm * 64 + mt * 16 + gg;
#pragma unroll
            for (int nt = 0; nt < 4; ++nt) {
                int col = wn * 32 + nt * 8 + tg * 2;
                *reinterpret_cast<__nv_bfloat162*>(tp + row0 * 136 + col) =
                    __floats2bfloat162_rn(acc[mt][nt][0], acc[mt][nt][1]);
                *reinterpret_cast<__nv_bfloat162*>(tp + (row0 + 8) * 136 + col) =
                    __floats2bfloat162_rn(acc[mt][nt][2], acc[mt][nt][3]);
            }
        }
        __syncthreads();

        // E/theta ladder, unrolled x7 (fixed 63 trips; tail predicated)
        float E = 0.f, th = 1e30f, invb = 1.f;
#pragma unroll 7
        for (int k = 0; k < 63; ++k) {
            float I = __bfloat162float(tp[(toff + k) * 136 + hh]);
            invb *= RINV;
            if (k < len) {
                float cc = fmaf(CSC, I, -3.0f);
                E  = fmaf(cc, invb, E);
                th = fminf(th, fmaf(V_DET, invb, -E));
            }
        }
        long idx = ((long)(2 * cch + q) * BATCH + b) * NHID + slab * 128 + hh;
        g_chkB[idx] = E * Afac;
        g_chkT[idx] = th;
    }

    // ---- completion: last chunk-CTA of batch b composes the sub-chunks ----
    __shared__ int s_done;
    __threadfence();
    __syncthreads();
    if (tid == 0) s_done = atomicAdd(&g_cnt[b], 1);
    __syncthreads();
    if (s_done != 7) return;
    __threadfence();    // acquire: make other CTAs' g_chk stores visible

    // 256 threads x 2 h each, 16 sub-chunks
    float v0 = V_RESET, v1 = V_RESET;
    int sp = 0;
#pragma unroll
    for (int s = 0; s < NSUB; ++s) {
        long i0 = ((long)s * BATCH + b) * NHID + tid;
        long i1 = i0 + 256;
        float t0f = g_chkT[i0], t1f = g_chkT[i1];
        float b0f = g_chkB[i0], b1f = g_chkB[i1];
        sp |= (v0 >= t0f) | (v1 >= t1f);
        float f = (s & 1) ? A62 : A63;
        v0 = fmaf(f, v0, b0f);
        v1 = fmaf(f, v1, b1f);
    }
    int any = __syncthreads_or(sp);
    if (tid == 0 && any) { atomicOr(&g_bspike[b], 1); atomicOr(&g_any, 1); }
    if (tid < NOUT) out[b * NOUT + tid] = 0.f;   // exact when spike-free
}

// -------- fallback bf16 GEMM (gated) + W_rec transpose -> x_proj [b][t][h] --
#define APITCH 264
#define BPITCH 72
#define SB_OFF (128 * APITCH)
#define SB_BUF (128 * BPITCH)
#define GEMM_SMEM ((SB_OFF + 2 * SB_BUF) * 2)

__global__ void __launch_bounds__(256, 2) gemm_fb_kernel(const float* __restrict__ x,
                                                         const float* __restrict__ W_in,
                                                         const float* __restrict__ W_rec) {
    if (g_any == 0) return;
    extern __shared__ __nv_bfloat16 smem2[];
    __nv_bfloat16* sA = smem2;
    __nv_bfloat16* sB = smem2 + SB_OFF;

    const int tid = threadIdx.x;
    const int warp = tid >> 5, lane = tid & 31;
    const int wm = warp & 1, wn = warp >> 1;
    const int g  = lane >> 2, tg = lane & 3;
    const int mat = lane >> 3, r8 = lane & 7;

    for (int j = blockIdx.x; j < NHID; j += 125) {
        g_wrecT[j * NHID + tid]       = W_rec[tid * NHID + j];
        g_wrecT[j * NHID + tid + 256] = W_rec[(tid + 256) * NHID + j];
    }

#pragma unroll 1
    for (int it = 0; it < 4; ++it) {
        const long tileM = ((long)blockIdx.x * 4 + it) * 128;
        __syncthreads();

#pragma unroll 4
        for (int i = 0; i < 32; ++i) {
            int idx = tid + i * 256;
            int r = idx >> 6, c4 = idx & 63;
            float4 v = *reinterpret_cast<const float4*>(x + (tileM + r) * NIN + c4 * 4);
            __nv_bfloat162 lo = __floats2bfloat162_rn(v.x, v.y);
            __nv_bfloat162 hi = __floats2bfloat162_rn(v.z, v.w);
            *reinterpret_cast<uint2*>(sA + r * APITCH + c4 * 4) =
                make_uint2(*reinterpret_cast<uint32_t*>(&lo),
                           *reinterpret_cast<uint32_t*>(&hi));
        }
#pragma unroll
        for (int i = 0; i < 4; ++i) {
            int idx = tid + i * 256;
            int r = idx >> 3, c8 = idx & 7;
            float4 a = *reinterpret_cast<const float4*>(W_in + (long)r * NIN + c8 * 8);
            float4 b2 = *reinterpret_cast<const float4*>(W_in + (long)r * NIN + c8 * 8 + 4);
            *reinterpret_cast<uint4*>(sB + r * BPITCH + c8 * 8) = cvt8_bf16(a, b2);
        }
        __syncthreads();

        const uint32_t sA32 = s2u(sA), sB32 = s2u(sB);
        uint32_t aBase[4];
#pragma unroll
        for (int mt = 0; mt < 4; ++mt)
            aBase[mt] = sA32 + (((wm * 64 + mt * 16 + (mat & 1) * 8 + r8) * APITCH)
                                + (mat >> 1) * 8) * 2;
        uint32_t bBase[2];
#pragma unroll
        for (int p2 = 0; p2 < 2; ++p2)
            bBase[p2] = (((wn * 32 + p2 * 16 + (mat >> 1) * 8 + r8) * BPITCH)
                         + (mat & 1) * 8) * 2;

        int p = 0;
#pragma unroll 1
        for (int slab = 0; slab < 4; ++slab) {
            float acc[4][4][4];
#pragma unroll
            for (int a = 0; a < 4; ++a)
#pragma unroll
                for (int b2 = 0; b2 < 4; ++b2)
#pragma unroll
                    for (int c = 0; c < 4; ++c) acc[a][b2][c] = 0.f;

#pragma unroll 1
            for (int kc = 0; kc < 4; ++kc) {
                int nkc = kc + 1, nslab = slab;
                if (nkc == 4) { nkc = 0; ++nslab; }
                const bool valid = (nslab < 4);
                uint4 br[4];
                if (valid) {
#pragma unroll
                    for (int i = 0; i < 4; ++i) {
                        int idx = tid + i * 256;
                        int r = idx >> 3, c8 = idx & 7;
                        const float* wp = W_in + (long)(nslab * 128 + r) * NIN
                                        + nkc * 64 + c8 * 8;
                        br[i] = cvt8_bf16(*reinterpret_cast<const float4*>(wp),
                                          *reinterpret_cast<const float4*>(wp + 4));
                    }
                }
                const uint32_t bufo = sB32 + p * (SB_BUF * 2);
#pragma unroll
                for (int ks = 0; ks < 4; ++ks) {
                    uint32_t af[4][4], bf[2][4];
#pragma unroll
                    for (int mt = 0; mt < 4; ++mt)
                        LDSM4(af[mt][0], af[mt][1], af[mt][2], af[mt][3],
                              aBase[mt] + (kc * 64 + ks * 16) * 2);
#pragma unroll
                    for (int p2 = 0; p2 < 2; ++p2)
                        LDSM4(bf[p2][0], bf[p2][1], bf[p2][2], bf[p2][3],
                              bufo + bBase[p2] + ks * 32);
#pragma unroll
                    for (int mt = 0; mt < 4; ++mt)
#pragma unroll
                        for (int nt = 0; nt < 4; ++nt)
                            MMA16816(acc[mt][nt],
                                     af[mt][0], af[mt][1], af[mt][2], af[mt][3],
                                     bf[nt >> 1][(nt & 1) * 2],
                                     bf[nt >> 1][(nt & 1) * 2 + 1]);
                }
                if (valid) {
#pragma unroll
                    for (int i = 0; i < 4; ++i) {
                        int idx = tid + i * 256;
                        int r = idx >> 3, c8 = idx & 7;
                        *reinterpret_cast<uint4*>(sB + (1 - p) * SB_BUF
                                                  + r * BPITCH + c8 * 8) = br[i];
                    }
                }
                __syncthreads();
                p ^= 1;
            }

#pragma unroll
            for (int mt = 0; mt < 4; ++mt) {
                long m0 = tileM + wm * 64 + mt * 16 + g;
                long b0 = m0 & 63, t0 = m0 >> 6;
                long m1 = m0 + 8;
                long b1 = m1 & 63, t1 = m1 >> 6;
                __nv_bfloat16* d0 = g_xproj + (b0 * T_STEPS + t0) * NHID;
                __nv_bfloat16* d1 = g_xproj + (b1 * T_STEPS + t1) * NHID;
#pragma unroll
                for (int nt = 0; nt < 4; ++nt) {
                    int col = slab * 128 + wn * 32 + nt * 8 + tg * 2;
                    *reinterpret_cast<__nv_bfloat162*>(d0 + col) =
                        __floats2bfloat162_rn(acc[mt][nt][0], acc[mt][nt][1]);
                    *reinterpret_cast<__nv_bfloat162*>(d1 + col) =
                        __floats2bfloat162_rn(acc[mt][nt][2], acc[mt][nt][3]);
                }
            }
        }
    }
}

// ------- fallback: full simulation + output projection (gated per batch) ----
#define PF2 8
__global__ void __launch_bounds__(128) scanfull_out_kernel(
        const float* __restrict__ W_out, float* __restrict__ out) {
    const int b = blockIdx.x;
    if (g_bspike[b] == 0) return;

    const int tid = threadIdx.x;
    __shared__ unsigned s_mask[16];
    __shared__ float sr[NHID];

    float v[4], a0[4], a1[4], psc[4], cnt[4];
#pragma unroll
    for (int i = 0; i < 4; ++i) {
        v[i] = V_RESET; a0[i] = 0.f; a1[i] = 0.f; psc[i] = 0.f; cnt[i] = 0.f;
    }
    const uint2* __restrict__ xp =
        reinterpret_cast<const uint2*>(g_xproj) + (long)b * (T_STEPS * NHID / 4) + tid;

    uint2 buf[PF2];
#pragma unroll
    for (int d = 0; d < PF2; ++d) buf[d] = xp[(long)d * (NHID / 4)];

    for (int t = 0; t < T_STEPS; t += PF2) {
#pragma unroll
        for (int d = 0; d < PF2; ++d) {
            uint2 raw = buf[d];
            int tn = t + d + PF2;
            if (tn > T_STEPS - 1) tn = T_STEPS - 1;
            buf[d] = xp[(long)tn * (NHID / 4)];

            float2 lo = __bfloat1622float2(*reinterpret_cast<__nv_bfloat162*>(&raw.x));
            float2 hi = __bfloat1622float2(*reinterpret_cast<__nv_bfloat162*>(&raw.y));
            float Ii[4] = {lo.x, lo.y, hi.x, hi.y};
            bool sp[4];
#pragma unroll
            for (int i = 0; i < 4; ++i) {
                float Itot  = Ii[i] + psc[i] + a0[i] + a1[i];
                float v_int = v[i] + DT_CM * Itot - DECAY_V * (v[i] - V_RESET);
                sp[i] = v_int >= V_TH;
                v[i]  = sp[i] ? V_RESET : v_int;
                a0[i] = a0[i] * D_ASC0 + (sp[i] ? AMP0 : 0.f);
                a1[i] = a1[i] * D_ASC1 + (sp[i] ? AMP1 : 0.f);
                cnt[i] += sp[i] ? 1.f : 0.f;
            }
            int anyl = (int)(sp[0] | sp[1] | sp[2] | sp[3]);

            if (__syncthreads_or(anyl)) {
                if (tid < 16) s_mask[tid] = 0;
                __syncthreads();
                unsigned nib = (unsigned)sp[0] | ((unsigned)sp[1] << 1)
                             | ((unsigned)sp[2] << 2) | ((unsigned)sp[3] << 3);
                if (nib) atomicOr(&s_mask[tid >> 3], nib << (4 * (tid & 7)));
                __syncthreads();
                float rec[4] = {0.f, 0.f, 0.f, 0.f};
#pragma unroll 1
                for (int w = 0; w < 16; ++w) {
                    unsigned word = s_mask[w];
                    while (word) {
                        int j = (w << 5) + __ffs(word) - 1;
                        word &= word - 1;
                        float4 wv = *reinterpret_cast<const float4*>(
                            g_wrecT + j * NHID + 4 * tid);
                        rec[0] += wv.x; rec[1] += wv.y;
                        rec[2] += wv.z; rec[3] += wv.w;
                    }
                }
                __syncthreads();
#pragma unroll
                for (int i = 0; i < 4; ++i) psc[i] = psc[i] * D_SYN + rec[i];
            } else {
#pragma unroll
                for (int i = 0; i < 4; ++i) psc[i] *= D_SYN;
            }
        }
    }

#pragma unroll
    for (int i = 0; i < 4; ++i) sr[4 * tid + i] = cnt[i] * (1.0f / T_STEPS);
    __syncthreads();

    float acc = 0.f;
    const float4* w = reinterpret_cast<const float4*>(W_out + tid * NHID);
#pragma unroll 4
    for (int i = 0; i < NHID / 4; ++i) {
        float4 wv = w[i];
        acc += wv.x * sr[4 * i] + wv.y * sr[4 * i + 1]
             + wv.z * sr[4 * i + 2] + wv.w * sr[4 * i + 3];
    }
    out[b * NOUT + tid] = acc;
}

// ---------------- launch ----------------
extern "C" void kernel_launch(void* const* d_in, const int* in_sizes, int n_in,
                              void* d_out, int out_size) {
    const float* x     = (const float*)d_in[0];
    const float* W_in  = (const float*)d_in[1];
    const float* W_rec = (const float*)d_in[2];
    const float* W_out = (const float*)d_in[3];
    float* out = (float*)d_out;
    (void)in_sizes; (void)n_in; (void)out_size;

    prep_kernel<<<65, 256>>>(W_in);

    cudaFuncSetAttribute(fused_kernel,
                         cudaFuncAttributeMaxDynamicSharedMemorySize, FUSED_SMEM);
    fused_kernel<<<8 * BATCH, 256, FUSED_SMEM>>>(x, out);

    cudaFuncSetAttribute(gemm_fb_kernel,
                         cudaFuncAttributeMaxDynamicSharedMemorySize, GEMM_SMEM);
    gemm_fb_kernel<<<125, 256, GEMM_SMEM>>>(x, W_in, W_rec);

    scanfull_out_kernel<<<BATCH, NOUT>>>(W_out, out);
}